// round 12
// baseline (speedup 1.0000x reference)
#include <cuda_runtime.h>
#include <cuda_fp16.h>
#include <math.h>

#define NQ 8192
#define NS 32768
#define NE 131072
#define DD 256
#define NH 8
#define HDIM 32
#define NGEO 128
#define NFFN 512

// ---------------- scratch (device globals; no allocation) ----------------
__device__ float  g_raw[NQ * 12];
__device__ float  g_x[NQ * DD];
__device__ int    g_rowptr[NQ + 1];

// half activations / weights
__device__ __half g_sf_h[NS * DD];
__device__ __half g_qt_h[NQ * DD];
__device__ __half g_geoh_h[NQ * NGEO];
__device__ __half g_geo_h[NQ * NGEO];
__device__ __half g_Qf_h[NQ * DD];
__device__ __half g_Kf_h[NS * DD];
__device__ __half g_Vf_h[NS * DD];
__device__ __half g_Gf_h[NQ * DD];
__device__ __half g_out_h[NQ * DD];
__device__ __half g_h1_h[NQ * NFFN];
__device__ __half g_Wq_h[DD * DD];
__device__ __half g_Wk_h[DD * DD];
__device__ __half g_Wv_h[DD * DD];
__device__ __half g_Wg_h[NGEO * DD];
__device__ __half g_Wo_h[DD * DD];
__device__ __half g_Wf1_h[DD * NFFN];
__device__ __half g_Wf2_h[NFFN * DD];
__device__ __half g_Gw2_h[NGEO * NGEO];

__device__ __forceinline__ float gelu_f(float x) {
    return 0.5f * x * (1.0f + erff(x * 0.7071067811865475f));
}

__device__ __forceinline__ void cpa16(void* dst, const void* src) {
    unsigned d = (unsigned)__cvta_generic_to_shared(dst);
    asm volatile("cp.async.cg.shared.global [%0], [%1], 16;" :: "r"(d), "l"(src));
}
__device__ __forceinline__ unsigned smem_u32(const void* p) {
    return (unsigned)__cvta_generic_to_shared(p);
}
__device__ __forceinline__ void unpack8(uint4 u, float* f) {
    float2 a = __half22float2(*(const __half2*)&u.x);
    float2 b = __half22float2(*(const __half2*)&u.y);
    float2 c = __half22float2(*(const __half2*)&u.z);
    float2 d = __half22float2(*(const __half2*)&u.w);
    f[0] = a.x; f[1] = a.y; f[2] = b.x; f[3] = b.y;
    f[4] = c.x; f[5] = c.y; f[6] = d.x; f[7] = d.y;
}
__device__ __forceinline__ float dot8(const float* q, uint4 u) {
    float k[8];
    unpack8(u, k);
    float d = 0.f;
    #pragma unroll
    for (int j = 0; j < 8; j++) d += q[j] * k[j];
    return d;
}

// ---------------- fused fp32 -> fp16 converts (weights + support_feats) --------
struct CvtJobs {
    const float* src[9];
    __half* dst[9];
    int n4[9];
};
__global__ void k_cvt_all(CvtJobs j) {
    int w = blockIdx.y;
    int i = blockIdx.x * blockDim.x + threadIdx.x;
    if (i >= j.n4[w]) return;
    float4 v = ((const float4*)j.src[w])[i];
    __half2 h0 = __floats2half2_rn(v.x, v.y);
    __half2 h1 = __floats2half2_rn(v.z, v.w);
    uint2 u;
    u.x = *(unsigned*)&h0;
    u.y = *(unsigned*)&h1;
    ((uint2*)j.dst[w])[i] = u;
}

// ---------------- row_ptr via boundary scan (q_idx sorted) ----------------
__global__ void k_bounds(const int* __restrict__ qidx) {
    int e = blockIdx.x * blockDim.x + threadIdx.x;
    if (e >= NE) return;
    int v = qidx[e];
    int prev = (e == 0) ? -1 : qidx[e - 1];
    for (int q = prev + 1; q <= v; q++) g_rowptr[q] = e;
    if (e == NE - 1) {
        for (int q = v + 1; q <= NQ; q++) g_rowptr[q] = NE;
    }
}

// ---------------- geo stats: warp per query ----------------
__global__ void k_geostats(const float* __restrict__ qpos,
                           const float* __restrict__ spos,
                           const int* __restrict__ sidx) {
    int warp = (blockIdx.x * blockDim.x + threadIdx.x) >> 5;
    int lane = threadIdx.x & 31;
    if (warp >= NQ) return;
    int q = warp;
    int st = g_rowptr[q], en = g_rowptr[q + 1];
    float qp0 = qpos[q * 3 + 0], qp1 = qpos[q * 3 + 1], qp2 = qpos[q * 3 + 2];
    float s0 = 0.f, s1 = 0.f, s2 = 0.f;
    float ss0 = 0.f, ss1 = 0.f, ss2 = 0.f;
    float mn0 = 1e30f, mn1 = 1e30f, mn2 = 1e30f;
    float mx0 = -1e30f, mx1 = -1e30f, mx2 = -1e30f;
    for (int e = st + lane; e < en; e += 32) {
        int s = sidx[e];
        float r0 = spos[s * 3 + 0] - qp0;
        float r1 = spos[s * 3 + 1] - qp1;
        float r2 = spos[s * 3 + 2] - qp2;
        s0 += r0; s1 += r1; s2 += r2;
        ss0 += r0 * r0; ss1 += r1 * r1; ss2 += r2 * r2;
        mn0 = fminf(mn0, r0); mn1 = fminf(mn1, r1); mn2 = fminf(mn2, r2);
        mx0 = fmaxf(mx0, r0); mx1 = fmaxf(mx1, r1); mx2 = fmaxf(mx2, r2);
    }
    #pragma unroll
    for (int off = 16; off > 0; off >>= 1) {
        s0 += __shfl_xor_sync(0xffffffffu, s0, off);
        s1 += __shfl_xor_sync(0xffffffffu, s1, off);
        s2 += __shfl_xor_sync(0xffffffffu, s2, off);
        ss0 += __shfl_xor_sync(0xffffffffu, ss0, off);
        ss1 += __shfl_xor_sync(0xffffffffu, ss1, off);
        ss2 += __shfl_xor_sync(0xffffffffu, ss2, off);
        mn0 = fminf(mn0, __shfl_xor_sync(0xffffffffu, mn0, off));
        mn1 = fminf(mn1, __shfl_xor_sync(0xffffffffu, mn1, off));
        mn2 = fminf(mn2, __shfl_xor_sync(0xffffffffu, mn2, off));
        mx0 = fmaxf(mx0, __shfl_xor_sync(0xffffffffu, mx0, off));
        mx1 = fmaxf(mx1, __shfl_xor_sync(0xffffffffu, mx1, off));
        mx2 = fmaxf(mx2, __shfl_xor_sync(0xffffffffu, mx2, off));
    }
    if (lane == 0) {
        float cnt = fmaxf((float)(en - st), 1.0f);
        float m0 = s0 / cnt, m1 = s1 / cnt, m2 = s2 / cnt;
        float v0 = fmaxf(ss0 / cnt - m0 * m0, 0.f);
        float v1 = fmaxf(ss1 / cnt - m1 * m1, 0.f);
        float v2 = fmaxf(ss2 / cnt - m2 * m2, 0.f);
        float* r = g_raw + q * 12;
        r[0] = m0; r[1] = m1; r[2] = m2;
        r[3] = sqrtf(v0); r[4] = sqrtf(v1); r[5] = sqrtf(v2);
        r[6] = fminf(fmaxf(mn0, -100.f), 100.f);
        r[7] = fminf(fmaxf(mn1, -100.f), 100.f);
        r[8] = fminf(fmaxf(mn2, -100.f), 100.f);
        r[9]  = fminf(fmaxf(mx0, -100.f), 100.f);
        r[10] = fminf(fmaxf(mx1, -100.f), 100.f);
        r[11] = fminf(fmaxf(mx2, -100.f), 100.f);
    }
}

// ---------------- LayerNorm: warp per row, fp32 in, fp16 out ----------------
__global__ void k_ln(const float* __restrict__ x, const float* __restrict__ g,
                     const float* __restrict__ b, __half* __restrict__ y) {
    int warp = (blockIdx.x * blockDim.x + threadIdx.x) >> 5;
    int lane = threadIdx.x & 31;
    if (warp >= NQ) return;
    const float4* xr = (const float4*)(x + warp * DD);
    float4 a = xr[lane * 2], c = xr[lane * 2 + 1];
    float sum = a.x + a.y + a.z + a.w + c.x + c.y + c.z + c.w;
    float ss = a.x * a.x + a.y * a.y + a.z * a.z + a.w * a.w +
               c.x * c.x + c.y * c.y + c.z * c.z + c.w * c.w;
    #pragma unroll
    for (int off = 16; off > 0; off >>= 1) {
        sum += __shfl_xor_sync(0xffffffffu, sum, off);
        ss  += __shfl_xor_sync(0xffffffffu, ss, off);
    }
    float mean = sum * (1.0f / 256.0f);
    float var = ss * (1.0f / 256.0f) - mean * mean;
    float rstd = rsqrtf(var + 1e-5f);
    const float4* gr = (const float4*)g;
    const float4* br = (const float4*)b;
    float4 g0 = gr[lane * 2], g1 = gr[lane * 2 + 1];
    float4 b0 = br[lane * 2], b1 = br[lane * 2 + 1];
    float o[8];
    o[0] = (a.x - mean) * rstd * g0.x + b0.x;
    o[1] = (a.y - mean) * rstd * g0.y + b0.y;
    o[2] = (a.z - mean) * rstd * g0.z + b0.z;
    o[3] = (a.w - mean) * rstd * g0.w + b0.w;
    o[4] = (c.x - mean) * rstd * g1.x + b1.x;
    o[5] = (c.y - mean) * rstd * g1.y + b1.y;
    o[6] = (c.z - mean) * rstd * g1.z + b1.z;
    o[7] = (c.w - mean) * rstd * g1.w + b1.w;
    __half2 h0 = __floats2half2_rn(o[0], o[1]);
    __half2 h1 = __floats2half2_rn(o[2], o[3]);
    __half2 h2 = __floats2half2_rn(o[4], o[5]);
    __half2 h3 = __floats2half2_rn(o[6], o[7]);
    uint4 u;
    u.x = *(unsigned*)&h0; u.y = *(unsigned*)&h1;
    u.z = *(unsigned*)&h2; u.w = *(unsigned*)&h3;
    ((uint4*)(y + (size_t)warp * DD))[lane] = u;
}

// ---------------- geo1: direct K=12 GEMM, warp per row, Gw1 in smem ------------
__global__ void k_geo1(const float* __restrict__ raw, const float* __restrict__ Gw1,
                       const float* __restrict__ Gb1, __half* __restrict__ C) {
    __shared__ float w[12 * NGEO];
    __shared__ float bsh[NGEO];
    int tid = threadIdx.x;
    for (int i = tid; i < 12 * NGEO; i += 256) w[i] = Gw1[i];
    if (tid < NGEO) bsh[tid] = Gb1[tid];
    __syncthreads();
    int row = blockIdx.x * 8 + (tid >> 5);
    int lane = tid & 31;
    float r[12];
    #pragma unroll
    for (int k = 0; k < 12; k++) r[k] = raw[row * 12 + k];
    #pragma unroll
    for (int j = 0; j < 4; j++) {
        int col = lane + 32 * j;        // conflict-free smem column access
        float s = bsh[col];
        #pragma unroll
        for (int k = 0; k < 12; k++) s = fmaf(r[k], w[k * NGEO + col], s);
        C[(size_t)row * NGEO + col] = __float2half_rn(gelu_f(s));
    }
}

// ---------------- FP16 tensor-core GEMM, BK=64, cp.async 2-stage ----------------
template <int BM, bool BIAS, bool GELU, bool RES, bool HOUT>
__device__ __forceinline__ void hgemm_body(
    const __half* __restrict__ A, const __half* __restrict__ B,
    const float* __restrict__ bias, const float* __restrict__ res,
    void* __restrict__ Cv, int N, int K, int m0, int n0) {
    constexpr int SA = 72, SB = 136;
    constexpr int MI = BM / 32;
    extern __shared__ __half smem[];
    __half (*As)[BM][SA] = reinterpret_cast<__half(*)[BM][SA]>(smem);
    __half (*Bs)[64][SB] = reinterpret_cast<__half(*)[64][SB]>(smem + 2 * BM * SA);

    int tid = threadIdx.x;
    int warp = tid >> 5, lane = tid & 31;
    int wm = warp & 1, wn = warp >> 1;
    int g = lane >> 2, t = lane & 3;

    float acc[MI][4][4];
    #pragma unroll
    for (int i = 0; i < MI; i++)
        #pragma unroll
        for (int j = 0; j < 4; j++)
            #pragma unroll
            for (int c = 0; c < 4; c++) acc[i][j][c] = 0.f;

    int KT = K >> 6;
    #pragma unroll
    for (int i = 0; i < BM / 32; i++) {
        int lin = tid + i * 256;
        int row = lin >> 3, col = (lin & 7) * 8;
        cpa16(&As[0][row][col], &A[(size_t)(m0 + row) * K + col]);
    }
    #pragma unroll
    for (int i = 0; i < 4; i++) {
        int lin = tid + i * 256;
        int row = lin >> 4, col = (lin & 15) * 8;
        cpa16(&Bs[0][row][col], &B[(size_t)row * N + n0 + col]);
    }
    asm volatile("cp.async.commit_group;");

    int buf = 0;
    for (int kt = 0; kt < KT; kt++) {
        if (kt + 1 < KT) {
            int k0 = (kt + 1) << 6;
            #pragma unroll
            for (int i = 0; i < BM / 32; i++) {
                int lin = tid + i * 256;
                int row = lin >> 3, col = (lin & 7) * 8;
                cpa16(&As[buf ^ 1][row][col], &A[(size_t)(m0 + row) * K + k0 + col]);
            }
            #pragma unroll
            for (int i = 0; i < 4; i++) {
                int lin = tid + i * 256;
                int row = lin >> 4, col = (lin & 15) * 8;
                cpa16(&Bs[buf ^ 1][row][col], &B[(size_t)(k0 + row) * N + n0 + col]);
            }
            asm volatile("cp.async.commit_group;");
            asm volatile("cp.async.wait_group 1;");
        } else {
            asm volatile("cp.async.wait_group 0;");
        }
        __syncthreads();
        #pragma unroll
        for (int ks = 0; ks < 64; ks += 16) {
            unsigned a[MI][4], b[4][2];
            #pragma unroll
            for (int mi = 0; mi < MI; mi++) {
                int row = wm * (BM / 2) + mi * 16 + (lane & 7) + ((lane >> 3) & 1) * 8;
                int col = ks + (lane >> 4) * 8;
                unsigned addr = smem_u32(&As[buf][row][col]);
                asm volatile(
                    "ldmatrix.sync.aligned.m8n8.x4.shared.b16 {%0,%1,%2,%3}, [%4];"
                    : "=r"(a[mi][0]), "=r"(a[mi][1]), "=r"(a[mi][2]), "=r"(a[mi][3])
                    : "r"(addr));
            }
            #pragma unroll
            for (int p = 0; p < 2; p++) {
                int krow = ks + (lane & 7) + ((lane >> 3) & 1) * 8;
                int ncol = wn * 32 + p * 16 + (lane >> 4) * 8;
                unsigned addr = smem_u32(&Bs[buf][krow][ncol]);
                unsigned r0, r1, r2, r3;
                asm volatile(
                    "ldmatrix.sync.aligned.m8n8.x4.trans.shared.b16 {%0,%1,%2,%3}, [%4];"
                    : "=r"(r0), "=r"(r1), "=r"(r2), "=r"(r3) : "r"(addr));
                b[2 * p][0] = r0; b[2 * p][1] = r1;
                b[2 * p + 1][0] = r2; b[2 * p + 1][1] = r3;
            }
            #pragma unroll
            for (int mi = 0; mi < MI; mi++)
                #pragma unroll
                for (int ni = 0; ni < 4; ni++) {
                    asm volatile(
                        "mma.sync.aligned.m16n8k16.row.col.f32.f16.f16.f32 "
                        "{%0,%1,%2,%3}, {%4,%5,%6,%7}, {%8,%9}, {%0,%1,%2,%3};"
                        : "+f"(acc[mi][ni][0]), "+f"(acc[mi][ni][1]),
                          "+f"(acc[mi][ni][2]), "+f"(acc[mi][ni][3])
                        : "r"(a[mi][0]), "r"(a[mi][1]), "r"(a[mi][2]), "r"(a[mi][3]),
                          "r"(b[ni][0]), "r"(b[ni][1]));
                }
        }
        buf ^= 1;
        __syncthreads();
    }
    #pragma unroll
    for (int mi = 0; mi < MI; mi++) {
        int mrow = m0 + wm * (BM / 2) + mi * 16 + g;
        #pragma unroll
        for (int ni = 0; ni < 4; ni++) {
            int ncol = n0 + wn * 32 + ni * 8 + 2 * t;
            #pragma unroll
            for (int half = 0; half < 2; half++) {
                int row = mrow + half * 8;
                float v0 = acc[mi][ni][half * 2 + 0];
                float v1 = acc[mi][ni][half * 2 + 1];
                if (BIAS) { v0 += bias[ncol]; v1 += bias[ncol + 1]; }
                if (GELU) { v0 = gelu_f(v0); v1 = gelu_f(v1); }
                if (RES) {
                    const float2 r = *(const float2*)&res[(size_t)row * N + ncol];
                    v0 += r.x; v1 += r.y;
                }
                if (HOUT) {
                    __half2 h = __floats2half2_rn(v0, v1);
                    *(__half2*)&((__half*)Cv)[(size_t)row * N + ncol] = h;
                } else {
                    float2 o; o.x = v0; o.y = v1;
                    *(float2*)&((float*)Cv)[(size_t)row * N + ncol] = o;
                }
            }
        }
    }
}

template <int BM, bool BIAS, bool GELU, bool RES, bool HOUT>
__global__ __launch_bounds__(256, 2)
void k_hgemm(const __half* __restrict__ A, const __half* __restrict__ B,
             const float* __restrict__ bias, const float* __restrict__ res,
             void* __restrict__ C, int N, int K) {
    hgemm_body<BM, BIAS, GELU, RES, HOUT>(A, B, bias, res, C, N, K,
                                          blockIdx.y * BM, blockIdx.x * 128);
}

// Merged K/V projection using the BK=64 body (A pre-converted to fp16).
__global__ __launch_bounds__(256, 2)
void k_hgemm_kv(const __half* __restrict__ A,
                const __half* __restrict__ B0, const __half* __restrict__ B1,
                __half* __restrict__ C0, __half* __restrict__ C1, int N, int K) {
    const __half* B = blockIdx.z ? B1 : B0;
    __half* C = blockIdx.z ? C1 : C0;
    hgemm_body<64, false, false, false, true>(A, B, nullptr, nullptr, C, N, K,
                                              blockIdx.y * 64, blockIdx.x * 128);
}

// ---------------- fused edge attention: warp/query, prefetched idx, 4-wide ------
__global__ void __launch_bounds__(256)
k_attn(const int* __restrict__ sidx, const float* __restrict__ log_tau) {
    int warp = (blockIdx.x * blockDim.x + threadIdx.x) >> 5;
    int lane = threadIdx.x & 31;
    if (warp >= NQ) return;
    int q = warp;
    int st = g_rowptr[q], en = g_rowptr[q + 1];
    float scale = 0.17677669529663689f * expf(-log_tau[0]);

    float qv[8];
    unpack8(((const uint4*)(g_Qf_h + (size_t)q * DD))[lane], qv);

    const uint4* Kf = (const uint4*)g_Kf_h;
    const uint4* Vf = (const uint4*)g_Vf_h;

    float m = 0.0f;
    float ssum = 0.0f;
    float a[8] = {0.f, 0.f, 0.f, 0.f, 0.f, 0.f, 0.f, 0.f};

    for (int base = st; base < en; base += 32) {
        int n = min(32, en - base);
        int myidx = (lane < n) ? sidx[base + lane] : 0;
        int i = 0;
        for (; i + 4 <= n; i += 4) {
            int s0 = __shfl_sync(0xffffffffu, myidx, i + 0);
            int s1 = __shfl_sync(0xffffffffu, myidx, i + 1);
            int s2 = __shfl_sync(0xffffffffu, myidx, i + 2);
            int s3 = __shfl_sync(0xffffffffu, myidx, i + 3);
            uint4 k0 = Kf[(size_t)s0 * 32 + lane];
            uint4 k1 = Kf[(size_t)s1 * 32 + lane];
            uint4 k2 = Kf[(size_t)s2 * 32 + lane];
            uint4 k3 = Kf[(size_t)s3 * 32 + lane];
            uint4 v0 = Vf[(size_t)s0 * 32 + lane];
            uint4 v1 = Vf[(size_t)s1 * 32 + lane];
            uint4 v2 = Vf[(size_t)s2 * 32 + lane];
            uint4 v3 = Vf[(size_t)s3 * 32 + lane];
            float d0 = dot8(qv, k0);
            float d1 = dot8(qv, k1);
            float d2 = dot8(qv, k2);
            float d3 = dot8(qv, k3);
            d0 += __shfl_xor_sync(0xffffffffu, d0, 1);
            d0 += __shfl_xor_sync(0xffffffffu, d0, 2);
            d1 += __shfl_xor_sync(0xffffffffu, d1, 1);
            d1 += __shfl_xor_sync(0xffffffffu, d1, 2);
            d2 += __shfl_xor_sync(0xffffffffu, d2, 1);
            d2 += __shfl_xor_sync(0xffffffffu, d2, 2);
            d3 += __shfl_xor_sync(0xffffffffu, d3, 1);
            d3 += __shfl_xor_sync(0xffffffffu, d3, 2);
            d0 *= scale; d1 *= scale; d2 *= scale; d3 *= scale;
            float mn = fmaxf(m, fmaxf(fmaxf(d0, d1), fmaxf(d2, d3)));
            float c  = __expf(m - mn);
            float r0 = __expf(d0 - mn);
            float r1 = __expf(d1 - mn);
            float r2 = __expf(d2 - mn);
            float r3 = __expf(d3 - mn);
            float vv0[8], vv1[8], vv2[8], vv3[8];
            unpack8(v0, vv0); unpack8(v1, vv1);
            unpack8(v2, vv2); unpack8(v3, vv3);
            #pragma unroll
            for (int j = 0; j < 8; j++)
                a[j] = a[j] * c + r0 * vv0[j] + r1 * vv1[j] + r2 * vv2[j] + r3 * vv3[j];
            ssum = ssum * c + r0 + r1 + r2 + r3;
            m = mn;
        }
        for (; i < n; i++) {
            int s = __shfl_sync(0xffffffffu, myidx, i);
            uint4 ku = Kf[(size_t)s * 32 + lane];
            uint4 vu = Vf[(size_t)s * 32 + lane];
            float d = dot8(qv, ku);
            d += __shfl_xor_sync(0xffffffffu, d, 1);
            d += __shfl_xor_sync(0xffffffffu, d, 2);
            d *= scale;
            float mn = fmaxf(m, d);
            float c = __expf(m - mn);
            float r = __expf(d - mn);
            float vv[8];
            unpack8(vu, vv);
            #pragma unroll
            for (int j = 0; j < 8; j++) a[j] = a[j] * c + r * vv[j];
            ssum = ssum * c + r;
            m = mn;
        }
    }

    float inv = 1.0f / fmaxf(ssum, 1e-8f);
    float gsc = ssum * inv;
    float gv[8];
    unpack8(((const uint4*)(g_Gf_h + (size_t)q * DD))[lane], gv);
    float o[8];
    #pragma unroll
    for (int j = 0; j < 8; j++) o[j] = a[j] * inv + gv[j] * gsc;
    __half2 h0 = __floats2half2_rn(o[0], o[1]);
    __half2 h1 = __floats2half2_rn(o[2], o[3]);
    __half2 h2 = __floats2half2_rn(o[4], o[5]);
    __half2 h3 = __floats2half2_rn(o[6], o[7]);
    uint4 u;
    u.x = *(unsigned*)&h0; u.y = *(unsigned*)&h1;
    u.z = *(unsigned*)&h2; u.w = *(unsigned*)&h3;
    ((uint4*)(g_out_h + (size_t)q * DD))[lane] = u;
}

// ---------------- host ----------------
template <typename T>
static T* symp(const void* sym) {
    void* p = nullptr;
    cudaGetSymbolAddress(&p, sym);
    return (T*)p;
}

#define SMEM_H64(BM) ((2 * (BM) * 72 + 2 * 64 * 136) * (int)sizeof(__half))

struct Ctx {
    cudaStream_t s1, s2;
    cudaEvent_t evRoot, evKV, evG;
    Ctx() {
        cudaStreamCreateWithFlags(&s1, cudaStreamNonBlocking);
        cudaStreamCreateWithFlags(&s2, cudaStreamNonBlocking);
        cudaEventCreateWithFlags(&evRoot, cudaEventDisableTiming);
        cudaEventCreateWithFlags(&evKV, cudaEventDisableTiming);
        cudaEventCreateWithFlags(&evG, cudaEventDisableTiming);
        cudaFuncSetAttribute((const void*)k_hgemm_kv,
            cudaFuncAttributeMaxDynamicSharedMemorySize, SMEM_H64(64));
        cudaFuncSetAttribute((const void*)k_hgemm<64, false, false, false, true>,
            cudaFuncAttributeMaxDynamicSharedMemorySize, SMEM_H64(64));
        cudaFuncSetAttribute((const void*)k_hgemm<64, true, true, false, true>,
            cudaFuncAttributeMaxDynamicSharedMemorySize, SMEM_H64(64));
        cudaFuncSetAttribute((const void*)k_hgemm<64, true, false, true, false>,
            cudaFuncAttributeMaxDynamicSharedMemorySize, SMEM_H64(64));
    }
};

extern "C" void kernel_launch(void* const* d_in, const int* in_sizes, int n_in,
                              void* d_out, int out_size) {
    const float* query_tokens  = (const float*)d_in[0];
    const float* query_pos     = (const float*)d_in[1];
    const float* support_feats = (const float*)d_in[2];
    const float* support_pos   = (const float*)d_in[3];
    const float* Wq   = (const float*)d_in[4];
    const float* Wk   = (const float*)d_in[5];
    const float* Wv   = (const float*)d_in[6];
    const float* Wg   = (const float*)d_in[7];
    const float* Wo   = (const float*)d_in[8];
    const float* bo   = (const float*)d_in[9];
    const float* log_tau = (const float*)d_in[10];
    const float* ln1_g = (const float*)d_in[11];
    const float* ln1_b = (const float*)d_in[12];
    const float* ln2_g = (const float*)d_in[13];
    const float* ln2_b = (const float*)d_in[14];
    const float* Wf1  = (const float*)d_in[15];
    const float* bf1  = (const float*)d_in[16];
    const float* Wf2  = (const float*)d_in[17];
    const float* bf2  = (const float*)d_in[18];
    const float* Gw1  = (const float*)d_in[19];
    const float* Gb1  = (const float*)d_in[20];
    const float* Gw2  = (const float*)d_in[21];
    const float* Gb2  = (const float*)d_in[22];
    const int* q_idx  = (const int*)d_in[23];
    const int* s_idx  = (const int*)d_in[24];
    float* out = (float*)d_out;

    float*  p_raw   = symp<float>(g_raw);
    float*  p_x     = symp<float>(g_x);
    __half* p_sf    = symp<__half>(g_sf_h);
    __half* p_qt    = symp<__half>(g_qt_h);
    __half* p_geoh  = symp<__half>(g_geoh_h);
    __half* p_geo   = symp<__half>(g_geo_h);
    __half* p_Qf    = symp<__half>(g_Qf_h);
    __half* p_Kf    = symp<__half>(g_Kf_h);
    __half* p_Vf    = symp<__half>(g_Vf_h);
    __half* p_Gf    = symp<__half>(g_Gf_h);
    __half* p_outh  = symp<__half>(g_out_h);
    __half* p_h1    = symp<__half>(g_h1_h);
    __half* p_Wq    = symp<__half>(g_Wq_h);
    __half* p_Wk    = symp<__half>(g_Wk_h);
    __half* p_Wv    = symp<__half>(g_Wv_h);
    __half* p_Wg    = symp<__half>(g_Wg_h);
    __half* p_Wo    = symp<__half>(g_Wo_h);
    __half* p_Wf1   = symp<__half>(g_Wf1_h);
    __half* p_Wf2   = symp<__half>(g_Wf2_h);
    __half* p_Gw2   = symp<__half>(g_Gw2_h);

    static Ctx ctx;

    // all fp32->fp16 converts in one launch (weights + support_feats), pre-fork
    CvtJobs jobs;
    jobs.src[0] = Wq;  jobs.dst[0] = p_Wq;  jobs.n4[0] = DD * DD / 4;
    jobs.src[1] = Wk;  jobs.dst[1] = p_Wk;  jobs.n4[1] = DD * DD / 4;
    jobs.src[2] = Wv;  jobs.dst[2] = p_Wv;  jobs.n4[2] = DD * DD / 4;
    jobs.src[3] = Wo;  jobs.dst[3] = p_Wo;  jobs.n4[3] = DD * DD / 4;
    jobs.src[4] = Wg;  jobs.dst[4] = p_Wg;  jobs.n4[4] = NGEO * DD / 4;
    jobs.src[5] = Gw2; jobs.dst[5] = p_Gw2; jobs.n4[5] = NGEO * NGEO / 4;
    jobs.src[6] = Wf1; jobs.dst[6] = p_Wf1; jobs.n4[6] = DD * NFFN / 4;
    jobs.src[7] = Wf2; jobs.dst[7] = p_Wf2; jobs.n4[7] = NFFN * DD / 4;
    jobs.src[8] = support_feats; jobs.dst[8] = p_sf; jobs.n4[8] = NS * DD / 4;
    k_cvt_all<<<dim3(NS * DD / 4 / 256, 9), 256>>>(jobs);

    // fork
    cudaEventRecord(ctx.evRoot, 0);
    cudaStreamWaitEvent(ctx.s1, ctx.evRoot, 0);
    cudaStreamWaitEvent(ctx.s2, ctx.evRoot, 0);

    // s1: merged K/V projection (BK=64 body, fp16 A)
    k_hgemm_kv<<<dim3(DD / 128, NS / 64, 2), 256, SMEM_H64(64), ctx.s1>>>(
        p_sf, p_Wk, p_Wv, p_Kf, p_Vf, DD, DD);
    cudaEventRecord(ctx.evKV, ctx.s1);

    // s2: geo chain
    k_bounds<<<NE / 256, 256, 0, ctx.s2>>>(q_idx);
    k_geostats<<<NQ / 8, 256, 0, ctx.s2>>>(query_pos, support_pos, s_idx);
    k_geo1<<<NQ / 8, 256, 0, ctx.s2>>>(p_raw, Gw1, Gb1, p_geoh);
    k_hgemm<64, true, true, false, true><<<dim3(NGEO / 128, NQ / 64), 256, SMEM_H64(64), ctx.s2>>>(
        p_geoh, p_Gw2, Gb2, nullptr, p_geo, NGEO, NGEO);
    k_hgemm<64, false, false, false, true><<<dim3(DD / 128, NQ / 64), 256, SMEM_H64(64), ctx.s2>>>(
        p_geo, p_Wg, nullptr, nullptr, p_Gf, DD, NGEO);
    cudaEventRecord(ctx.evG, ctx.s2);

    // s0 (default): query chain
    k_ln<<<NQ / 8, 256>>>(query_tokens, ln1_g, ln1_b, p_qt);
    k_hgemm<64, false, false, false, true><<<dim3(DD / 128, NQ / 64), 256, SMEM_H64(64)>>>(
        p_qt, p_Wq, nullptr, nullptr, p_Qf, DD, DD);

    // join, fused edge attention
    cudaStreamWaitEvent(0, ctx.evKV, 0);
    cudaStreamWaitEvent(0, ctx.evG, 0);
    k_attn<<<NQ / 8, 256>>>(s_idx, log_tau);

    // tail
    k_hgemm<64, true, false, true, false><<<dim3(DD / 128, NQ / 64), 256, SMEM_H64(64)>>>(
        p_outh, p_Wo, bo, query_tokens, p_x, DD, DD);
    k_ln<<<NQ / 8, 256>>>(p_x, ln2_g, ln2_b, p_qt);
    k_hgemm<64, true, true, false, true><<<dim3(NFFN / 128, NQ / 64), 256, SMEM_H64(64)>>>(
        p_qt, p_Wf1, bf1, nullptr, p_h1, NFFN, DD);
    k_hgemm<64, true, false, true, false><<<dim3(DD / 128, NQ / 64), 256, SMEM_H64(64)>>>(
        p_h1, p_Wf2, bf2, p_x, out, DD, NFFN);
}

// round 13
// speedup vs baseline: 1.2240x; 1.2240x over previous
#include <cuda_runtime.h>
#include <cuda_fp16.h>
#include <math.h>

#define NQ 8192
#define NS 32768
#define NE 131072
#define DD 256
#define NH 8
#define HDIM 32
#define NGEO 128
#define NFFN 512

// ---------------- scratch (device globals; no allocation) ----------------
__device__ float  g_raw[NQ * 12];
__device__ float  g_x[NQ * DD];
__device__ int    g_rowptr[NQ + 1];

// half activations / weights
__device__ __half g_qt_h[NQ * DD];
__device__ __half g_geoh_h[NQ * NGEO];
__device__ __half g_geo_h[NQ * NGEO];
__device__ __half g_Qf_h[NQ * DD];
__device__ __half g_Kf_h[NS * DD];
__device__ __half g_Vf_h[NS * DD];
__device__ __half g_Gf_h[NQ * DD];
__device__ __half g_out_h[NQ * DD];
__device__ __half g_h1_h[NQ * NFFN];
__device__ __half g_Wq_h[DD * DD];
__device__ __half g_Wk_h[DD * DD];
__device__ __half g_Wv_h[DD * DD];
__device__ __half g_Wg_h[NGEO * DD];
__device__ __half g_Wo_h[DD * DD];
__device__ __half g_Wf1_h[DD * NFFN];
__device__ __half g_Wf2_h[NFFN * DD];
__device__ __half g_Gw2_h[NGEO * NGEO];

__device__ __forceinline__ float gelu_f(float x) {
    return 0.5f * x * (1.0f + erff(x * 0.7071067811865475f));
}

__device__ __forceinline__ void cpa16(void* dst, const void* src) {
    unsigned d = (unsigned)__cvta_generic_to_shared(dst);
    asm volatile("cp.async.cg.shared.global [%0], [%1], 16;" :: "r"(d), "l"(src));
}
__device__ __forceinline__ unsigned smem_u32(const void* p) {
    return (unsigned)__cvta_generic_to_shared(p);
}
__device__ __forceinline__ void unpack8(uint4 u, float* f) {
    float2 a = __half22float2(*(const __half2*)&u.x);
    float2 b = __half22float2(*(const __half2*)&u.y);
    float2 c = __half22float2(*(const __half2*)&u.z);
    float2 d = __half22float2(*(const __half2*)&u.w);
    f[0] = a.x; f[1] = a.y; f[2] = b.x; f[3] = b.y;
    f[4] = c.x; f[5] = c.y; f[6] = d.x; f[7] = d.y;
}
__device__ __forceinline__ float dot8(const float* q, uint4 u) {
    float k[8];
    unpack8(u, k);
    float d = 0.f;
    #pragma unroll
    for (int j = 0; j < 8; j++) d += q[j] * k[j];
    return d;
}

// ---------------- fused fp32 -> fp16 weight converts ----------------
struct CvtJobs {
    const float* src[8];
    __half* dst[8];
    int n4[8];
};
__global__ void k_cvt_all(CvtJobs j) {
    int w = blockIdx.y;
    int i = blockIdx.x * blockDim.x + threadIdx.x;
    if (i >= j.n4[w]) return;
    float4 v = ((const float4*)j.src[w])[i];
    __half2 h0 = __floats2half2_rn(v.x, v.y);
    __half2 h1 = __floats2half2_rn(v.z, v.w);
    uint2 u;
    u.x = *(unsigned*)&h0;
    u.y = *(unsigned*)&h1;
    ((uint2*)j.dst[w])[i] = u;
}

// ---------------- row_ptr via boundary scan (q_idx sorted) ----------------
__global__ void k_bounds(const int* __restrict__ qidx) {
    int e = blockIdx.x * blockDim.x + threadIdx.x;
    if (e >= NE) return;
    int v = qidx[e];
    int prev = (e == 0) ? -1 : qidx[e - 1];
    for (int q = prev + 1; q <= v; q++) g_rowptr[q] = e;
    if (e == NE - 1) {
        for (int q = v + 1; q <= NQ; q++) g_rowptr[q] = NE;
    }
}

// ---------------- geo stats: warp per query ----------------
__global__ void k_geostats(const float* __restrict__ qpos,
                           const float* __restrict__ spos,
                           const int* __restrict__ sidx) {
    int warp = (blockIdx.x * blockDim.x + threadIdx.x) >> 5;
    int lane = threadIdx.x & 31;
    if (warp >= NQ) return;
    int q = warp;
    int st = g_rowptr[q], en = g_rowptr[q + 1];
    float qp0 = qpos[q * 3 + 0], qp1 = qpos[q * 3 + 1], qp2 = qpos[q * 3 + 2];
    float s0 = 0.f, s1 = 0.f, s2 = 0.f;
    float ss0 = 0.f, ss1 = 0.f, ss2 = 0.f;
    float mn0 = 1e30f, mn1 = 1e30f, mn2 = 1e30f;
    float mx0 = -1e30f, mx1 = -1e30f, mx2 = -1e30f;
    for (int e = st + lane; e < en; e += 32) {
        int s = sidx[e];
        float r0 = spos[s * 3 + 0] - qp0;
        float r1 = spos[s * 3 + 1] - qp1;
        float r2 = spos[s * 3 + 2] - qp2;
        s0 += r0; s1 += r1; s2 += r2;
        ss0 += r0 * r0; ss1 += r1 * r1; ss2 += r2 * r2;
        mn0 = fminf(mn0, r0); mn1 = fminf(mn1, r1); mn2 = fminf(mn2, r2);
        mx0 = fmaxf(mx0, r0); mx1 = fmaxf(mx1, r1); mx2 = fmaxf(mx2, r2);
    }
    #pragma unroll
    for (int off = 16; off > 0; off >>= 1) {
        s0 += __shfl_xor_sync(0xffffffffu, s0, off);
        s1 += __shfl_xor_sync(0xffffffffu, s1, off);
        s2 += __shfl_xor_sync(0xffffffffu, s2, off);
        ss0 += __shfl_xor_sync(0xffffffffu, ss0, off);
        ss1 += __shfl_xor_sync(0xffffffffu, ss1, off);
        ss2 += __shfl_xor_sync(0xffffffffu, ss2, off);
        mn0 = fminf(mn0, __shfl_xor_sync(0xffffffffu, mn0, off));
        mn1 = fminf(mn1, __shfl_xor_sync(0xffffffffu, mn1, off));
        mn2 = fminf(mn2, __shfl_xor_sync(0xffffffffu, mn2, off));
        mx0 = fmaxf(mx0, __shfl_xor_sync(0xffffffffu, mx0, off));
        mx1 = fmaxf(mx1, __shfl_xor_sync(0xffffffffu, mx1, off));
        mx2 = fmaxf(mx2, __shfl_xor_sync(0xffffffffu, mx2, off));
    }
    if (lane == 0) {
        float cnt = fmaxf((float)(en - st), 1.0f);
        float m0 = s0 / cnt, m1 = s1 / cnt, m2 = s2 / cnt;
        float v0 = fmaxf(ss0 / cnt - m0 * m0, 0.f);
        float v1 = fmaxf(ss1 / cnt - m1 * m1, 0.f);
        float v2 = fmaxf(ss2 / cnt - m2 * m2, 0.f);
        float* r = g_raw + q * 12;
        r[0] = m0; r[1] = m1; r[2] = m2;
        r[3] = sqrtf(v0); r[4] = sqrtf(v1); r[5] = sqrtf(v2);
        r[6] = fminf(fmaxf(mn0, -100.f), 100.f);
        r[7] = fminf(fmaxf(mn1, -100.f), 100.f);
        r[8] = fminf(fmaxf(mn2, -100.f), 100.f);
        r[9]  = fminf(fmaxf(mx0, -100.f), 100.f);
        r[10] = fminf(fmaxf(mx1, -100.f), 100.f);
        r[11] = fminf(fmaxf(mx2, -100.f), 100.f);
    }
}

// ---------------- LayerNorm: warp per row, fp32 in, fp16 out ----------------
__global__ void k_ln(const float* __restrict__ x, const float* __restrict__ g,
                     const float* __restrict__ b, __half* __restrict__ y) {
    int warp = (blockIdx.x * blockDim.x + threadIdx.x) >> 5;
    int lane = threadIdx.x & 31;
    if (warp >= NQ) return;
    const float4* xr = (const float4*)(x + warp * DD);
    float4 a = xr[lane * 2], c = xr[lane * 2 + 1];
    float sum = a.x + a.y + a.z + a.w + c.x + c.y + c.z + c.w;
    float ss = a.x * a.x + a.y * a.y + a.z * a.z + a.w * a.w +
               c.x * c.x + c.y * c.y + c.z * c.z + c.w * c.w;
    #pragma unroll
    for (int off = 16; off > 0; off >>= 1) {
        sum += __shfl_xor_sync(0xffffffffu, sum, off);
        ss  += __shfl_xor_sync(0xffffffffu, ss, off);
    }
    float mean = sum * (1.0f / 256.0f);
    float var = ss * (1.0f / 256.0f) - mean * mean;
    float rstd = rsqrtf(var + 1e-5f);
    const float4* gr = (const float4*)g;
    const float4* br = (const float4*)b;
    float4 g0 = gr[lane * 2], g1 = gr[lane * 2 + 1];
    float4 b0 = br[lane * 2], b1 = br[lane * 2 + 1];
    float o[8];
    o[0] = (a.x - mean) * rstd * g0.x + b0.x;
    o[1] = (a.y - mean) * rstd * g0.y + b0.y;
    o[2] = (a.z - mean) * rstd * g0.z + b0.z;
    o[3] = (a.w - mean) * rstd * g0.w + b0.w;
    o[4] = (c.x - mean) * rstd * g1.x + b1.x;
    o[5] = (c.y - mean) * rstd * g1.y + b1.y;
    o[6] = (c.z - mean) * rstd * g1.z + b1.z;
    o[7] = (c.w - mean) * rstd * g1.w + b1.w;
    __half2 h0 = __floats2half2_rn(o[0], o[1]);
    __half2 h1 = __floats2half2_rn(o[2], o[3]);
    __half2 h2 = __floats2half2_rn(o[4], o[5]);
    __half2 h3 = __floats2half2_rn(o[6], o[7]);
    uint4 u;
    u.x = *(unsigned*)&h0; u.y = *(unsigned*)&h1;
    u.z = *(unsigned*)&h2; u.w = *(unsigned*)&h3;
    ((uint4*)(y + (size_t)warp * DD))[lane] = u;
}

// ---------------- geo1: direct K=12 GEMM, warp per row, Gw1 in smem ------------
__global__ void k_geo1(const float* __restrict__ raw, const float* __restrict__ Gw1,
                       const float* __restrict__ Gb1, __half* __restrict__ C) {
    __shared__ float w[12 * NGEO];
    __shared__ float bsh[NGEO];
    int tid = threadIdx.x;
    for (int i = tid; i < 12 * NGEO; i += 256) w[i] = Gw1[i];
    if (tid < NGEO) bsh[tid] = Gb1[tid];
    __syncthreads();
    int row = blockIdx.x * 8 + (tid >> 5);
    int lane = tid & 31;
    float r[12];
    #pragma unroll
    for (int k = 0; k < 12; k++) r[k] = raw[row * 12 + k];
    #pragma unroll
    for (int j = 0; j < 4; j++) {
        int col = lane + 32 * j;        // conflict-free smem column access
        float s = bsh[col];
        #pragma unroll
        for (int k = 0; k < 12; k++) s = fmaf(r[k], w[k * NGEO + col], s);
        C[(size_t)row * NGEO + col] = __float2half_rn(gelu_f(s));
    }
}

// ---------------- FP16 tensor-core GEMM, BK=64, cp.async 2-stage ----------------
template <int BM, bool BIAS, bool GELU, bool RES, bool HOUT>
__device__ __forceinline__ void hgemm_body(
    const __half* __restrict__ A, const __half* __restrict__ B,
    const float* __restrict__ bias, const float* __restrict__ res,
    void* __restrict__ Cv, int N, int K, int m0, int n0) {
    constexpr int SA = 72, SB = 136;
    constexpr int MI = BM / 32;
    extern __shared__ __half smem[];
    __half (*As)[BM][SA] = reinterpret_cast<__half(*)[BM][SA]>(smem);
    __half (*Bs)[64][SB] = reinterpret_cast<__half(*)[64][SB]>(smem + 2 * BM * SA);

    int tid = threadIdx.x;
    int warp = tid >> 5, lane = tid & 31;
    int wm = warp & 1, wn = warp >> 1;
    int g = lane >> 2, t = lane & 3;

    float acc[MI][4][4];
    #pragma unroll
    for (int i = 0; i < MI; i++)
        #pragma unroll
        for (int j = 0; j < 4; j++)
            #pragma unroll
            for (int c = 0; c < 4; c++) acc[i][j][c] = 0.f;

    int KT = K >> 6;
    #pragma unroll
    for (int i = 0; i < BM / 32; i++) {
        int lin = tid + i * 256;
        int row = lin >> 3, col = (lin & 7) * 8;
        cpa16(&As[0][row][col], &A[(size_t)(m0 + row) * K + col]);
    }
    #pragma unroll
    for (int i = 0; i < 4; i++) {
        int lin = tid + i * 256;
        int row = lin >> 4, col = (lin & 15) * 8;
        cpa16(&Bs[0][row][col], &B[(size_t)row * N + n0 + col]);
    }
    asm volatile("cp.async.commit_group;");

    int buf = 0;
    for (int kt = 0; kt < KT; kt++) {
        if (kt + 1 < KT) {
            int k0 = (kt + 1) << 6;
            #pragma unroll
            for (int i = 0; i < BM / 32; i++) {
                int lin = tid + i * 256;
                int row = lin >> 3, col = (lin & 7) * 8;
                cpa16(&As[buf ^ 1][row][col], &A[(size_t)(m0 + row) * K + k0 + col]);
            }
            #pragma unroll
            for (int i = 0; i < 4; i++) {
                int lin = tid + i * 256;
                int row = lin >> 4, col = (lin & 15) * 8;
                cpa16(&Bs[buf ^ 1][row][col], &B[(size_t)(k0 + row) * N + n0 + col]);
            }
            asm volatile("cp.async.commit_group;");
            asm volatile("cp.async.wait_group 1;");
        } else {
            asm volatile("cp.async.wait_group 0;");
        }
        __syncthreads();
        #pragma unroll
        for (int ks = 0; ks < 64; ks += 16) {
            unsigned a[MI][4], b[4][2];
            #pragma unroll
            for (int mi = 0; mi < MI; mi++) {
                int row = wm * (BM / 2) + mi * 16 + (lane & 7) + ((lane >> 3) & 1) * 8;
                int col = ks + (lane >> 4) * 8;
                unsigned addr = smem_u32(&As[buf][row][col]);
                asm volatile(
                    "ldmatrix.sync.aligned.m8n8.x4.shared.b16 {%0,%1,%2,%3}, [%4];"
                    : "=r"(a[mi][0]), "=r"(a[mi][1]), "=r"(a[mi][2]), "=r"(a[mi][3])
                    : "r"(addr));
            }
            #pragma unroll
            for (int p = 0; p < 2; p++) {
                int krow = ks + (lane & 7) + ((lane >> 3) & 1) * 8;
                int ncol = wn * 32 + p * 16 + (lane >> 4) * 8;
                unsigned addr = smem_u32(&Bs[buf][krow][ncol]);
                unsigned r0, r1, r2, r3;
                asm volatile(
                    "ldmatrix.sync.aligned.m8n8.x4.trans.shared.b16 {%0,%1,%2,%3}, [%4];"
                    : "=r"(r0), "=r"(r1), "=r"(r2), "=r"(r3) : "r"(addr));
                b[2 * p][0] = r0; b[2 * p][1] = r1;
                b[2 * p + 1][0] = r2; b[2 * p + 1][1] = r3;
            }
            #pragma unroll
            for (int mi = 0; mi < MI; mi++)
                #pragma unroll
                for (int ni = 0; ni < 4; ni++) {
                    asm volatile(
                        "mma.sync.aligned.m16n8k16.row.col.f32.f16.f16.f32 "
                        "{%0,%1,%2,%3}, {%4,%5,%6,%7}, {%8,%9}, {%0,%1,%2,%3};"
                        : "+f"(acc[mi][ni][0]), "+f"(acc[mi][ni][1]),
                          "+f"(acc[mi][ni][2]), "+f"(acc[mi][ni][3])
                        : "r"(a[mi][0]), "r"(a[mi][1]), "r"(a[mi][2]), "r"(a[mi][3]),
                          "r"(b[ni][0]), "r"(b[ni][1]));
                }
        }
        buf ^= 1;
        __syncthreads();
    }
    #pragma unroll
    for (int mi = 0; mi < MI; mi++) {
        int mrow = m0 + wm * (BM / 2) + mi * 16 + g;
        #pragma unroll
        for (int ni = 0; ni < 4; ni++) {
            int ncol = n0 + wn * 32 + ni * 8 + 2 * t;
            #pragma unroll
            for (int half = 0; half < 2; half++) {
                int row = mrow + half * 8;
                float v0 = acc[mi][ni][half * 2 + 0];
                float v1 = acc[mi][ni][half * 2 + 1];
                if (BIAS) { v0 += bias[ncol]; v1 += bias[ncol + 1]; }
                if (GELU) { v0 = gelu_f(v0); v1 = gelu_f(v1); }
                if (RES) {
                    const float2 r = *(const float2*)&res[(size_t)row * N + ncol];
                    v0 += r.x; v1 += r.y;
                }
                if (HOUT) {
                    __half2 h = __floats2half2_rn(v0, v1);
                    *(__half2*)&((__half*)Cv)[(size_t)row * N + ncol] = h;
                } else {
                    float2 o; o.x = v0; o.y = v1;
                    *(float2*)&((float*)Cv)[(size_t)row * N + ncol] = o;
                }
            }
        }
    }
}

template <int BM, bool BIAS, bool GELU, bool RES, bool HOUT>
__global__ __launch_bounds__(256, 2)
void k_hgemm(const __half* __restrict__ A, const __half* __restrict__ B,
             const float* __restrict__ bias, const float* __restrict__ res,
             void* __restrict__ C, int N, int K) {
    hgemm_body<BM, BIAS, GELU, RES, HOUT>(A, B, bias, res, C, N, K,
                                          blockIdx.y * BM, blockIdx.x * 128);
}

// ---------------- KV projection with in-kernel fp32->fp16 A convert, BK=32 ------
__global__ __launch_bounds__(256, 2)
void k_hgemm_kvf(const float* __restrict__ A,
                 const __half* __restrict__ B0, const __half* __restrict__ B1,
                 __half* __restrict__ C0, __half* __restrict__ C1, int N, int K) {
    constexpr int BM = 64, SA32 = 36, SA = 40, SB = 136, MI = 2;
    extern __shared__ __align__(16) char smraw[];
    float  (*A32)[BM][SA32] = reinterpret_cast<float(*)[BM][SA32]>(smraw);
    __half (*A16)[SA]       = reinterpret_cast<__half(*)[SA]>(smraw + 2 * BM * SA32 * 4);
    __half (*Bs)[32][SB]    = reinterpret_cast<__half(*)[32][SB]>(
                                  smraw + 2 * BM * SA32 * 4 + BM * SA * 2);
    const __half* B = blockIdx.z ? B1 : B0;
    __half* C = blockIdx.z ? C1 : C0;
    int m0 = blockIdx.y * BM, n0 = blockIdx.x * 128;

    int tid = threadIdx.x;
    int warp = tid >> 5, lane = tid & 31;
    int wm = warp & 1, wn = warp >> 1;
    int g = lane >> 2, t = lane & 3;

    float acc[MI][4][4];
    #pragma unroll
    for (int i = 0; i < MI; i++)
        #pragma unroll
        for (int j = 0; j < 4; j++)
            #pragma unroll
            for (int c = 0; c < 4; c++) acc[i][j][c] = 0.f;

    int KT = K >> 5;
    #pragma unroll
    for (int i = 0; i < 2; i++) {
        int lin = tid + i * 256;
        int row = lin >> 3, colq = (lin & 7) * 4;
        cpa16(&A32[0][row][colq], &A[(size_t)(m0 + row) * K + colq]);
    }
    #pragma unroll
    for (int i = 0; i < 2; i++) {
        int lin = tid + i * 256;
        int row = lin >> 4, col = (lin & 15) * 8;
        cpa16(&Bs[0][row][col], &B[(size_t)row * N + n0 + col]);
    }
    asm volatile("cp.async.commit_group;");

    int buf = 0;
    for (int kt = 0; kt < KT; kt++) {
        if (kt + 1 < KT) {
            int k0 = (kt + 1) << 5;
            #pragma unroll
            for (int i = 0; i < 2; i++) {
                int lin = tid + i * 256;
                int row = lin >> 3, colq = (lin & 7) * 4;
                cpa16(&A32[buf ^ 1][row][colq], &A[(size_t)(m0 + row) * K + k0 + colq]);
            }
            #pragma unroll
            for (int i = 0; i < 2; i++) {
                int lin = tid + i * 256;
                int row = lin >> 4, col = (lin & 15) * 8;
                cpa16(&Bs[buf ^ 1][row][col], &B[(size_t)(k0 + row) * N + n0 + col]);
            }
            asm volatile("cp.async.commit_group;");
            asm volatile("cp.async.wait_group 1;");
        } else {
            asm volatile("cp.async.wait_group 0;");
        }
        __syncthreads();
        {
            int row = tid >> 2, c0 = (tid & 3) * 8;
            const float* src = &A32[buf][row][c0];
            float4 f0 = *(const float4*)(src + 0);
            float4 f1 = *(const float4*)(src + 4);
            __half2 h0 = __floats2half2_rn(f0.x, f0.y);
            __half2 h1 = __floats2half2_rn(f0.z, f0.w);
            __half2 h2 = __floats2half2_rn(f1.x, f1.y);
            __half2 h3 = __floats2half2_rn(f1.z, f1.w);
            uint4 u;
            u.x = *(unsigned*)&h0; u.y = *(unsigned*)&h1;
            u.z = *(unsigned*)&h2; u.w = *(unsigned*)&h3;
            *(uint4*)&A16[row][c0] = u;
        }
        __syncthreads();
        #pragma unroll
        for (int ks = 0; ks < 32; ks += 16) {
            unsigned a[MI][4], b[4][2];
            #pragma unroll
            for (int mi = 0; mi < MI; mi++) {
                int row = wm * (BM / 2) + mi * 16 + (lane & 7) + ((lane >> 3) & 1) * 8;
                int col = ks + (lane >> 4) * 8;
                unsigned addr = smem_u32(&A16[row][col]);
                asm volatile(
                    "ldmatrix.sync.aligned.m8n8.x4.shared.b16 {%0,%1,%2,%3}, [%4];"
                    : "=r"(a[mi][0]), "=r"(a[mi][1]), "=r"(a[mi][2]), "=r"(a[mi][3])
                    : "r"(addr));
            }
            #pragma unroll
            for (int p = 0; p < 2; p++) {
                int krow = ks + (lane & 7) + ((lane >> 3) & 1) * 8;
                int ncol = wn * 32 + p * 16 + (lane >> 4) * 8;
                unsigned addr = smem_u32(&Bs[buf][krow][ncol]);
                unsigned r0, r1, r2, r3;
                asm volatile(
                    "ldmatrix.sync.aligned.m8n8.x4.trans.shared.b16 {%0,%1,%2,%3}, [%4];"
                    : "=r"(r0), "=r"(r1), "=r"(r2), "=r"(r3) : "r"(addr));
                b[2 * p][0] = r0; b[2 * p][1] = r1;
                b[2 * p + 1][0] = r2; b[2 * p + 1][1] = r3;
            }
            #pragma unroll
            for (int mi = 0; mi < MI; mi++)
                #pragma unroll
                for (int ni = 0; ni < 4; ni++) {
                    asm volatile(
                        "mma.sync.aligned.m16n8k16.row.col.f32.f16.f16.f32 "
                        "{%0,%1,%2,%3}, {%4,%5,%6,%7}, {%8,%9}, {%0,%1,%2,%3};"
                        : "+f"(acc[mi][ni][0]), "+f"(acc[mi][ni][1]),
                          "+f"(acc[mi][ni][2]), "+f"(acc[mi][ni][3])
                        : "r"(a[mi][0]), "r"(a[mi][1]), "r"(a[mi][2]), "r"(a[mi][3]),
                          "r"(b[ni][0]), "r"(b[ni][1]));
                }
        }
        buf ^= 1;
    }
    #pragma unroll
    for (int mi = 0; mi < MI; mi++) {
        int mrow = m0 + wm * (BM / 2) + mi * 16 + g;
        #pragma unroll
        for (int ni = 0; ni < 4; ni++) {
            int ncol = n0 + wn * 32 + ni * 8 + 2 * t;
            #pragma unroll
            for (int half = 0; half < 2; half++) {
                int row = mrow + half * 8;
                __half2 h = __floats2half2_rn(acc[mi][ni][half * 2 + 0],
                                              acc[mi][ni][half * 2 + 1]);
                *(__half2*)&C[(size_t)row * N + ncol] = h;
            }
        }
    }
}

// ---------------- fused edge attention: warp/query, prefetched idx, 4-wide ------
__global__ void __launch_bounds__(256)
k_attn(const int* __restrict__ sidx, const float* __restrict__ log_tau) {
    int warp = (blockIdx.x * blockDim.x + threadIdx.x) >> 5;
    int lane = threadIdx.x & 31;
    if (warp >= NQ) return;
    int q = warp;
    int st = g_rowptr[q], en = g_rowptr[q + 1];
    float scale = 0.17677669529663689f * expf(-log_tau[0]);

    float qv[8];
    unpack8(((const uint4*)(g_Qf_h + (size_t)q * DD))[lane], qv);

    const uint4* Kf = (const uint4*)g_Kf_h;
    const uint4* Vf = (const uint4*)g_Vf_h;

    float m = 0.0f;
    float ssum = 0.0f;
    float a[8] = {0.f, 0.f, 0.f, 0.f, 0.f, 0.f, 0.f, 0.f};

    for (int base = st; base < en; base += 32) {
        int n = min(32, en - base);
        int myidx = (lane < n) ? sidx[base + lane] : 0;
        int i = 0;
        for (; i + 4 <= n; i += 4) {
            int s0 = __shfl_sync(0xffffffffu, myidx, i + 0);
            int s1 = __shfl_sync(0xffffffffu, myidx, i + 1);
            int s2 = __shfl_sync(0xffffffffu, myidx, i + 2);
            int s3 = __shfl_sync(0xffffffffu, myidx, i + 3);
            uint4 k0 = Kf[(size_t)s0 * 32 + lane];
            uint4 k1 = Kf[(size_t)s1 * 32 + lane];
            uint4 k2 = Kf[(size_t)s2 * 32 + lane];
            uint4 k3 = Kf[(size_t)s3 * 32 + lane];
            uint4 v0 = Vf[(size_t)s0 * 32 + lane];
            uint4 v1 = Vf[(size_t)s1 * 32 + lane];
            uint4 v2 = Vf[(size_t)s2 * 32 + lane];
            uint4 v3 = Vf[(size_t)s3 * 32 + lane];
            float d0 = dot8(qv, k0);
            float d1 = dot8(qv, k1);
            float d2 = dot8(qv, k2);
            float d3 = dot8(qv, k3);
            d0 += __shfl_xor_sync(0xffffffffu, d0, 1);
            d0 += __shfl_xor_sync(0xffffffffu, d0, 2);
            d1 += __shfl_xor_sync(0xffffffffu, d1, 1);
            d1 += __shfl_xor_sync(0xffffffffu, d1, 2);
            d2 += __shfl_xor_sync(0xffffffffu, d2, 1);
            d2 += __shfl_xor_sync(0xffffffffu, d2, 2);
            d3 += __shfl_xor_sync(0xffffffffu, d3, 1);
            d3 += __shfl_xor_sync(0xffffffffu, d3, 2);
            d0 *= scale; d1 *= scale; d2 *= scale; d3 *= scale;
            float mn = fmaxf(m, fmaxf(fmaxf(d0, d1), fmaxf(d2, d3)));
            float c  = __expf(m - mn);
            float r0 = __expf(d0 - mn);
            float r1 = __expf(d1 - mn);
            float r2 = __expf(d2 - mn);
            float r3 = __expf(d3 - mn);
            float vv0[8], vv1[8], vv2[8], vv3[8];
            unpack8(v0, vv0); unpack8(v1, vv1);
            unpack8(v2, vv2); unpack8(v3, vv3);
            #pragma unroll
            for (int j = 0; j < 8; j++)
                a[j] = a[j] * c + r0 * vv0[j] + r1 * vv1[j] + r2 * vv2[j] + r3 * vv3[j];
            ssum = ssum * c + r0 + r1 + r2 + r3;
            m = mn;
        }
        for (; i < n; i++) {
            int s = __shfl_sync(0xffffffffu, myidx, i);
            uint4 ku = Kf[(size_t)s * 32 + lane];
            uint4 vu = Vf[(size_t)s * 32 + lane];
            float d = dot8(qv, ku);
            d += __shfl_xor_sync(0xffffffffu, d, 1);
            d += __shfl_xor_sync(0xffffffffu, d, 2);
            d *= scale;
            float mn = fmaxf(m, d);
            float c = __expf(m - mn);
            float r = __expf(d - mn);
            float vv[8];
            unpack8(vu, vv);
            #pragma unroll
            for (int j = 0; j < 8; j++) a[j] = a[j] * c + r * vv[j];
            ssum = ssum * c + r;
            m = mn;
        }
    }

    float inv = 1.0f / fmaxf(ssum, 1e-8f);
    float gsc = ssum * inv;
    float gv[8];
    unpack8(((const uint4*)(g_Gf_h + (size_t)q * DD))[lane], gv);
    float o[8];
    #pragma unroll
    for (int j = 0; j < 8; j++) o[j] = a[j] * inv + gv[j] * gsc;
    __half2 h0 = __floats2half2_rn(o[0], o[1]);
    __half2 h1 = __floats2half2_rn(o[2], o[3]);
    __half2 h2 = __floats2half2_rn(o[4], o[5]);
    __half2 h3 = __floats2half2_rn(o[6], o[7]);
    uint4 u;
    u.x = *(unsigned*)&h0; u.y = *(unsigned*)&h1;
    u.z = *(unsigned*)&h2; u.w = *(unsigned*)&h3;
    ((uint4*)(g_out_h + (size_t)q * DD))[lane] = u;
}

// ---------------- host ----------------
template <typename T>
static T* symp(const void* sym) {
    void* p = nullptr;
    cudaGetSymbolAddress(&p, sym);
    return (T*)p;
}

#define SMEM_H64(BM) ((2 * (BM) * 72 + 2 * 64 * 136) * (int)sizeof(__half))
#define SMEM_KVF (2 * 64 * 36 * 4 + 64 * 40 * 2 + 2 * 32 * 136 * 2)

struct Ctx {
    cudaStream_t s1, s2;
    cudaEvent_t evRoot, evKV, evG;
    Ctx() {
        cudaStreamCreateWithFlags(&s1, cudaStreamNonBlocking);
        cudaStreamCreateWithFlags(&s2, cudaStreamNonBlocking);
        cudaEventCreateWithFlags(&evRoot, cudaEventDisableTiming);
        cudaEventCreateWithFlags(&evKV, cudaEventDisableTiming);
        cudaEventCreateWithFlags(&evG, cudaEventDisableTiming);
        cudaFuncSetAttribute((const void*)k_hgemm_kvf,
            cudaFuncAttributeMaxDynamicSharedMemorySize, SMEM_KVF);
        cudaFuncSetAttribute((const void*)k_hgemm<64, false, false, false, true>,
            cudaFuncAttributeMaxDynamicSharedMemorySize, SMEM_H64(64));
        cudaFuncSetAttribute((const void*)k_hgemm<64, true, true, false, true>,
            cudaFuncAttributeMaxDynamicSharedMemorySize, SMEM_H64(64));
        cudaFuncSetAttribute((const void*)k_hgemm<64, true, false, true, false>,
            cudaFuncAttributeMaxDynamicSharedMemorySize, SMEM_H64(64));
    }
};

extern "C" void kernel_launch(void* const* d_in, const int* in_sizes, int n_in,
                              void* d_out, int out_size) {
    const float* query_tokens  = (const float*)d_in[0];
    const float* query_pos     = (const float*)d_in[1];
    const float* support_feats = (const float*)d_in[2];
    const float* support_pos   = (const float*)d_in[3];
    const float* Wq   = (const float*)d_in[4];
    const float* Wk   = (const float*)d_in[5];
    const float* Wv   = (const float*)d_in[6];
    const float* Wg   = (const float*)d_in[7];
    const float* Wo   = (const float*)d_in[8];
    const float* bo   = (const float*)d_in[9];
    const float* log_tau = (const float*)d_in[10];
    const float* ln1_g = (const float*)d_in[11];
    const float* ln1_b = (const float*)d_in[12];
    const float* ln2_g = (const float*)d_in[13];
    const float* ln2_b = (const float*)d_in[14];
    const float* Wf1  = (const float*)d_in[15];
    const float* bf1  = (const float*)d_in[16];
    const float* Wf2  = (const float*)d_in[17];
    const float* bf2  = (const float*)d_in[18];
    const float* Gw1  = (const float*)d_in[19];
    const float* Gb1  = (const float*)d_in[20];
    const float* Gw2  = (const float*)d_in[21];
    const float* Gb2  = (const float*)d_in[22];
    const int* q_idx  = (const int*)d_in[23];
    const int* s_idx  = (const int*)d_in[24];
    float* out = (float*)d_out;

    float*  p_raw   = symp<float>(g_raw);
    float*  p_x     = symp<float>(g_x);
    __half* p_qt    = symp<__half>(g_qt_h);
    __half* p_geoh  = symp<__half>(g_geoh_h);
    __half* p_geo   = symp<__half>(g_geo_h);
    __half* p_Qf    = symp<__half>(g_Qf_h);
    __half* p_Kf    = symp<__half>(g_Kf_h);
    __half* p_Vf    = symp<__half>(g_Vf_h);
    __half* p_Gf    = symp<__half>(g_Gf_h);
    __half* p_outh  = symp<__half>(g_out_h);
    __half* p_h1    = symp<__half>(g_h1_h);
    __half* p_Wq    = symp<__half>(g_Wq_h);
    __half* p_Wk    = symp<__half>(g_Wk_h);
    __half* p_Wv    = symp<__half>(g_Wv_h);
    __half* p_Wg    = symp<__half>(g_Wg_h);
    __half* p_Wo    = symp<__half>(g_Wo_h);
    __half* p_Wf1   = symp<__half>(g_Wf1_h);
    __half* p_Wf2   = symp<__half>(g_Wf2_h);
    __half* p_Gw2   = symp<__half>(g_Gw2_h);

    static Ctx ctx;

    // all weight converts in one launch, pre-fork
    CvtJobs jobs;
    jobs.src[0] = Wq;  jobs.dst[0] = p_Wq;  jobs.n4[0] = DD * DD / 4;
    jobs.src[1] = Wk;  jobs.dst[1] = p_Wk;  jobs.n4[1] = DD * DD / 4;
    jobs.src[2] = Wv;  jobs.dst[2] = p_Wv;  jobs.n4[2] = DD * DD / 4;
    jobs.src[3] = Wo;  jobs.dst[3] = p_Wo;  jobs.n4[3] = DD * DD / 4;
    jobs.src[4] = Wg;  jobs.dst[4] = p_Wg;  jobs.n4[4] = NGEO * DD / 4;
    jobs.src[5] = Gw2; jobs.dst[5] = p_Gw2; jobs.n4[5] = NGEO * NGEO / 4;
    jobs.src[6] = Wf1; jobs.dst[6] = p_Wf1; jobs.n4[6] = DD * NFFN / 4;
    jobs.src[7] = Wf2; jobs.dst[7] = p_Wf2; jobs.n4[7] = NFFN * DD / 4;
    k_cvt_all<<<dim3(DD * NFFN / 4 / 256, 8), 256>>>(jobs);

    // fork
    cudaEventRecord(ctx.evRoot, 0);
    cudaStreamWaitEvent(ctx.s1, ctx.evRoot, 0);
    cudaStreamWaitEvent(ctx.s2, ctx.evRoot, 0);

    // s1: merged K/V projection (A converted in-kernel)
    k_hgemm_kvf<<<dim3(DD / 128, NS / 64, 2), 256, SMEM_KVF, ctx.s1>>>(
        support_feats, p_Wk, p_Wv, p_Kf, p_Vf, DD, DD);
    cudaEventRecord(ctx.evKV, ctx.s1);

    // s2: geo chain
    k_bounds<<<NE / 256, 256, 0, ctx.s2>>>(q_idx);
    k_geostats<<<NQ / 8, 256, 0, ctx.s2>>>(query_pos, support_pos, s_idx);
    k_geo1<<<NQ / 8, 256, 0, ctx.s2>>>(p_raw, Gw1, Gb1, p_geoh);
    k_hgemm<64, true, true, false, true><<<dim3(NGEO / 128, NQ / 64), 256, SMEM_H64(64), ctx.s2>>>(
        p_geoh, p_Gw2, Gb2, nullptr, p_geo, NGEO, NGEO);
    k_hgemm<64, false, false, false, true><<<dim3(DD / 128, NQ / 64), 256, SMEM_H64(64), ctx.s2>>>(
        p_geo, p_Wg, nullptr, nullptr, p_Gf, DD, NGEO);
    cudaEventRecord(ctx.evG, ctx.s2);

    // s0 (default): query chain
    k_ln<<<NQ / 8, 256>>>(query_tokens, ln1_g, ln1_b, p_qt);
    k_hgemm<64, false, false, false, true><<<dim3(DD / 128, NQ / 64), 256, SMEM_H64(64)>>>(
        p_qt, p_Wq, nullptr, nullptr, p_Qf, DD, DD);

    // join, fused edge attention
    cudaStreamWaitEvent(0, ctx.evKV, 0);
    cudaStreamWaitEvent(0, ctx.evG, 0);
    k_attn<<<NQ / 8, 256>>>(s_idx, log_tau);

    // tail
    k_hgemm<64, true, false, true, false><<<dim3(DD / 128, NQ / 64), 256, SMEM_H64(64)>>>(
        p_outh, p_Wo, bo, query_tokens, p_x, DD, DD);
    k_ln<<<NQ / 8, 256>>>(p_x, ln2_g, ln2_b, p_qt);
    k_hgemm<64, true, true, false, true><<<dim3(NFFN / 128, NQ / 64), 256, SMEM_H64(64)>>>(
        p_qt, p_Wf1, bf1, nullptr, p_h1, NFFN, DD);
    k_hgemm<64, true, false, true, false><<<dim3(DD / 128, NQ / 64), 256, SMEM_H64(64)>>>(
        p_h1, p_Wf2, bf2, p_x, out, DD, NFFN);
}